// round 7
// baseline (speedup 1.0000x reference)
#include <cuda_runtime.h>

#define B 32
#define S 1024
#define W 512
#define D 768
#define NPOS 32
#define NT 192           // = D/4 threads, one float4 column per thread
#define TOTW (B * W)     // 16384 words
#define NBLK 1480        // persistent CTAs; ids >= NBLK come from the queue

__device__ int g_ctr;

__global__ void reset_ctr_kernel() { g_ctr = NBLK; }

struct Meta { int id, start, len, p, valid; };

__device__ __forceinline__ Meta load_meta(int id,
                                          const int* __restrict__ word_lens,
                                          const int* __restrict__ seq_len,
                                          const int* __restrict__ pos)
{
    Meta m;
    m.id = id;
    const int w = id & (W - 1);
    const int b = id >> 9;
    const int start = __ldg(&word_lens[id]);
    const int nxt   = (w + 1 < W) ? __ldg(&word_lens[id + 1]) : 0;
    const int end   = (nxt == 0) ? __ldg(&seq_len[b]) : nxt;
    int len = end - start;
    if (len < 1) len = 1;
    m.start = start;
    m.len   = len;
    m.p     = __ldg(&pos[id]);
    m.valid = (start != 0) || (w == 0);
    return m;
}

__global__ void __launch_bounds__(NT) charpool_steal_kernel(
    const float* __restrict__ feats,      // [B, S, D]
    const int* __restrict__ word_lens,    // [B, W]
    const int* __restrict__ seq_len,      // [B]
    const int* __restrict__ pos,          // [B, W]
    const float* __restrict__ pos_table,  // [NPOS, D]
    float* __restrict__ out)              // [B, W, D]
{
    __shared__ Meta s_meta[2];

    const int t = threadIdx.x;
    const int dq = D / 4;
    const float4* __restrict__ ptab = reinterpret_cast<const float4*>(pos_table);

    // iteration 0: static assignment = blockIdx.x
    if (t == 0)
        s_meta[0] = load_meta(blockIdx.x, word_lens, seq_len, pos);
    __syncthreads();

    int buf = 0;
    for (;;) {
        const Meta m = s_meta[buf];
        if (m.id >= TOTW) break;

        // ---- thread 0: steal next task; its atomic + meta-load latency
        //      overlaps the whole CTA's feats processing below ----
        Meta nm;
        if (t == 0) {
            const int nid = atomicAdd(&g_ctr, 1);
            if (nid < TOTW) {
                nm = load_meta(nid, word_lens, seq_len, pos);
            } else {
                nm.id = TOTW; nm.start = 0; nm.len = 1; nm.p = 0; nm.valid = 0;
            }
        }

        // ---- all threads: process word m ----
        const float4 pt = ptab[m.p * dq + t];
        float4 r;
        if (m.valid) {
            const float4* fp = reinterpret_cast<const float4*>(
                feats + ((size_t)(m.id >> 9) * S + (size_t)m.start) * D) + t;
            float4 acc = make_float4(0.f, 0.f, 0.f, 0.f);
            const float4 z = make_float4(0.f, 0.f, 0.f, 0.f);
            const int len = m.len;
            for (int s = 0; s < len; s += 4) {
                float4 v0 = fp[0 * dq];
                float4 v1 = (s + 1 < len) ? fp[1 * dq] : z;
                float4 v2 = (s + 2 < len) ? fp[2 * dq] : z;
                float4 v3 = (s + 3 < len) ? fp[3 * dq] : z;
                acc.x += (v0.x + v1.x) + (v2.x + v3.x);
                acc.y += (v0.y + v1.y) + (v2.y + v3.y);
                acc.z += (v0.z + v1.z) + (v2.z + v3.z);
                acc.w += (v0.w + v1.w) + (v2.w + v3.w);
                fp += 4 * dq;
            }
            const float inv = 1.0f / (float)len;
            r.x = fmaf(acc.x, inv, pt.x);
            r.y = fmaf(acc.y, inv, pt.y);
            r.z = fmaf(acc.z, inv, pt.z);
            r.w = fmaf(acc.w, inv, pt.w);
        } else {
            r = pt;   // pos=0 table row is zero -> zeros for padding words
        }
        __stcs(reinterpret_cast<float4*>(out + (size_t)m.id * D) + t, r);

        // ---- publish next task and advance ----
        if (t == 0) s_meta[buf ^ 1] = nm;
        __syncthreads();
        buf ^= 1;
    }
}

extern "C" void kernel_launch(void* const* d_in, const int* in_sizes, int n_in,
                              void* d_out, int out_size)
{
    const float* feats     = (const float*)d_in[0];
    const int*   word_lens = (const int*)d_in[1];
    const int*   seq_len   = (const int*)d_in[2];
    const int*   pos       = (const int*)d_in[3];
    const float* pos_table = (const float*)d_in[4];
    float* out = (float*)d_out;

    reset_ctr_kernel<<<1, 1>>>();
    charpool_steal_kernel<<<NBLK, NT>>>(feats, word_lens, seq_len, pos, pos_table, out);
}

// round 9
// speedup vs baseline: 1.5046x; 1.5046x over previous
#include <cuda_runtime.h>

#define B 32
#define S 1024
#define W 512
#define D 768
#define NPOS 32
#define NT 192            // = D/4 threads, one float4 column per thread
#define TOTW (B * W)      // 16384 words
#define CPS 8             // CTAs per SM (forced via launch_bounds)
#define NBLK (148 * CPS)  // 1184: exactly one resident wave on 148 SMs

__global__ void __launch_bounds__(NT, CPS) charpool_persist_kernel(
    const float* __restrict__ feats,      // [B, S, D]
    const int* __restrict__ word_lens,    // [B, W]
    const int* __restrict__ seq_len,      // [B]
    const int* __restrict__ pos,          // [B, W]
    const float* __restrict__ pos_table,  // [NPOS, D]
    float* __restrict__ out)              // [B, W, D]
{
    const int t = threadIdx.x;
    const int dq = D / 4;
    const float4* __restrict__ ptab = reinterpret_cast<const float4*>(pos_table);

    int id = blockIdx.x;
    if (id >= TOTW) return;

    // metadata for first word
    int start = __ldg(&word_lens[id]);
    int nxt   = ((id & (W - 1)) + 1 < W) ? __ldg(&word_lens[id + 1]) : 0;
    int p     = __ldg(&pos[id]);
    int sl    = __ldg(&seq_len[id >> 9]);

    for (;;) {
        // ---- prefetch next word's metadata (overlaps current feats latency) ----
        const int nid  = id + NBLK;
        const bool more = (nid < TOTW);
        int n_start = 0, n_nxt = 0, n_p = 0, n_sl = 0;
        if (more) {
            n_start = __ldg(&word_lens[nid]);
            n_nxt   = ((nid & (W - 1)) + 1 < W) ? __ldg(&word_lens[nid + 1]) : 0;
            n_p     = __ldg(&pos[nid]);
            n_sl    = __ldg(&seq_len[nid >> 9]);
        }

        // ---- process current word ----
        const int b   = id >> 9;
        const int w   = id & (W - 1);
        const int end = (nxt == 0) ? sl : nxt;
        const bool valid = (start != 0) || (w == 0);

        const float4 pt = ptab[p * dq + t];
        float4 r;

        if (valid) {
            int len = end - start;
            if (len < 1) len = 1;
            const float4* fp = reinterpret_cast<const float4*>(
                feats + ((size_t)b * S + (size_t)start) * D) + t;

            float4 acc = make_float4(0.f, 0.f, 0.f, 0.f);
            const float4 z = make_float4(0.f, 0.f, 0.f, 0.f);
            for (int s = 0; s < len; s += 4) {
                // up to 4 independent row loads issued before any consume
                float4 v0 = fp[0 * dq];
                float4 v1 = (s + 1 < len) ? fp[1 * dq] : z;
                float4 v2 = (s + 2 < len) ? fp[2 * dq] : z;
                float4 v3 = (s + 3 < len) ? fp[3 * dq] : z;
                acc.x += (v0.x + v1.x) + (v2.x + v3.x);
                acc.y += (v0.y + v1.y) + (v2.y + v3.y);
                acc.z += (v0.z + v1.z) + (v2.z + v3.z);
                acc.w += (v0.w + v1.w) + (v2.w + v3.w);
                fp += 4 * dq;
            }
            const float inv = 1.0f / (float)len;
            r.x = fmaf(acc.x, inv, pt.x);
            r.y = fmaf(acc.y, inv, pt.y);
            r.z = fmaf(acc.z, inv, pt.z);
            r.w = fmaf(acc.w, inv, pt.w);
        } else {
            r = pt;  // pos=0 row of the table is zero -> zeros for padding words
        }

        // streaming store: out has zero reuse; don't displace L2-resident feats
        __stcs(reinterpret_cast<float4*>(out + (size_t)id * D) + t, r);

        if (!more) break;
        id = nid;
        start = n_start; nxt = n_nxt; p = n_p; sl = n_sl;
    }
}

extern "C" void kernel_launch(void* const* d_in, const int* in_sizes, int n_in,
                              void* d_out, int out_size)
{
    const float* feats     = (const float*)d_in[0];
    const int*   word_lens = (const int*)d_in[1];
    const int*   seq_len   = (const int*)d_in[2];
    const int*   pos       = (const int*)d_in[3];
    const float* pos_table = (const float*)d_in[4];
    float* out = (float*)d_out;

    charpool_persist_kernel<<<NBLK, NT>>>(feats, word_lens, seq_len, pos, pos_table, out);
}